// round 7
// baseline (speedup 1.0000x reference)
#include <cuda_runtime.h>

#define N_Q   8192
#define M_T   50000
#define DIM   128
#define K_NN  10
#define NCLS  10
#define QT    32      // queries per block (one per lane)
#define CT    8       // train rows per warp-chunk
#define WARPS 8

// Stable sorted-insert: strict < keeps earlier-seen (lower index) on ties,
// matching jax.lax.top_k tie-breaking within a scan stream.
__device__ __forceinline__ void topk_insert(float s, int id,
                                            float (&kd)[K_NN], int (&ki)[K_NN]) {
#pragma unroll
    for (int p = 0; p < K_NN; ++p) {
        if (s < kd[p]) {
            float tf = kd[p]; kd[p] = s; s = tf;
            int   ti = ki[p]; ki[p] = id; id = ti;
        }
    }
}

// Probe label buffer dtype from its first 32 entries.
// mode 1: int64, mode 2: float32-encoded, mode 0: int32 (default).
__device__ __forceinline__ int detect_label_mode(const void* lp) {
    const long long* i64 = (const long long*)lp;
    bool ok64 = true;
#pragma unroll
    for (int i = 0; i < 32; ++i) { long long v = i64[i]; if (v < 0 || v >= NCLS) ok64 = false; }
    if (ok64) return 1;
    const int* i32 = (const int*)lp;
    bool ok32 = true;
#pragma unroll
    for (int i = 0; i < 32; ++i) { int v = i32[i]; if (v < 0 || v >= NCLS) ok32 = false; }
    if (ok32) return 0;
    const float* f32 = (const float*)lp;
    bool okf = true;
#pragma unroll
    for (int i = 0; i < 32; ++i) {
        float f = f32[i];
        if (!(f >= 0.f && f < (float)NCLS && f == rintf(f))) okf = false;
    }
    if (okf) return 2;
    return 0;
}

__device__ __forceinline__ int read_label(const void* lp, int idx, int mode) {
    if (mode == 1) return (int)((const long long*)lp)[idx];
    if (mode == 2) return (int)rintf(((const float*)lp)[idx]);
    return ((const int*)lp)[idx];
}

// ONE kernel: distances + top-k + merge + vote. Static 48 KB smem only.
// OUTPUT IS WRITTEN AS FLOAT32 (this round's single variable change).
__global__ __launch_bounds__(256) void knn_all(
        const float* __restrict__ x, const float* __restrict__ tp,
        const void* __restrict__ label, float* __restrict__ out) {
    __shared__ float4 sh4[3072];                 // 48 KB, phase-overlaid

    const int tid  = threadIdx.x;
    const int w    = tid >> 5;
    const int lane = tid & 31;
    const int qb   = blockIdx.x * QT;

    // ---- Phase 1 layout: qT [128][32] floats (16KB) + per-warp train chunks (32KB)
    float*  qT  = (float*)sh4;
    float4* Tb4 = sh4 + 1024 + w * (CT * 32);    // this warp's 8 rows x 32 float4

    // Load query tile transposed: qT[dim][q] -> lane-indexed reads conflict-free.
    for (int idx = tid; idx < QT * DIM; idx += 256) {
        int q  = idx >> 7;
        int d0 = idx & (DIM - 1);
        qT[d0 * QT + q] = x[(size_t)(qb + q) * DIM + d0];
    }
    __syncthreads();

    float kd[K_NN]; int ki[K_NN];
#pragma unroll
    for (int i = 0; i < K_NN; ++i) { kd[i] = 3.4e38f; ki[i] = 0; }

    // Each warp scans a strided partition of ALL train rows.
    for (int cb = w * CT; cb < M_T; cb += WARPS * CT) {
        float y2r[CT];
        // Chunk load + inline y2 (butterfly reduce -> every lane holds row sum).
#pragma unroll
        for (int it = 0; it < CT; ++it) {
            int g = cb + it;
            float4 v = make_float4(0.f, 0.f, 0.f, 0.f);
            if (g < M_T) v = ((const float4*)(tp + (size_t)g * DIM))[lane];
            Tb4[it * 32 + lane] = v;
            float p = v.x * v.x + v.y * v.y + v.z * v.z + v.w * v.w;
#pragma unroll
            for (int o = 16; o > 0; o >>= 1) p += __shfl_xor_sync(0xffffffffu, p, o);
            y2r[it] = p;
        }
        __syncwarp();

        float acc[CT];
#pragma unroll
        for (int t = 0; t < CT; ++t) acc[t] = 0.f;

#pragma unroll 1
        for (int sec = 0; sec < 8; ++sec) {           // 16 dims per section
            float qv[16];
#pragma unroll
            for (int j = 0; j < 16; ++j) qv[j] = qT[(sec * 16 + j) * QT + lane];
#pragma unroll
            for (int j4 = 0; j4 < 4; ++j4) {
#pragma unroll
                for (int t = 0; t < CT; ++t) {
                    float4 v = Tb4[t * 32 + sec * 4 + j4];   // warp-uniform broadcast
                    acc[t] = fmaf(qv[j4 * 4 + 0], v.x, acc[t]);
                    acc[t] = fmaf(qv[j4 * 4 + 1], v.y, acc[t]);
                    acc[t] = fmaf(qv[j4 * 4 + 2], v.z, acc[t]);
                    acc[t] = fmaf(qv[j4 * 4 + 3], v.w, acc[t]);
                }
            }
        }

        // score = y2 - 2*dot : same ordering as reference's x2 + y2 - 2*dot.
#pragma unroll
        for (int t = 0; t < CT; ++t) {
            int g = cb + t;
            if (g < M_T) {
                float s = fmaf(-2.0f, acc[t], y2r[t]);
                if (s < kd[K_NN - 1]) topk_insert(s, g, kd, ki);
            }
        }
        __syncwarp();
    }

    // ---- Phase 2: in-block merge of per-warp top-k, then vote. Overlay smem.
    __syncthreads();                              // everyone done with qT/Tb
    float* md = (float*)sh4;                      // [WARPS*QT][K_NN] floats (10KB)
    int*   mi = (int*)(md + WARPS * QT * K_NN);   // [WARPS*QT][K_NN] ints   (10KB)

#pragma unroll
    for (int j = 0; j < K_NN; ++j) {
        md[(w * QT + lane) * K_NN + j] = kd[j];
        mi[(w * QT + lane) * K_NN + j] = ki[j];
    }
    __syncthreads();

    if (tid < QT) {                               // one thread per query
        float fd[K_NN]; int fi[K_NN];
#pragma unroll
        for (int i = 0; i < K_NN; ++i) { fd[i] = 3.4e38f; fi[i] = 0; }
        for (int ww = 0; ww < WARPS; ++ww) {
#pragma unroll
            for (int j = 0; j < K_NN; ++j) {
                float d = md[(ww * QT + tid) * K_NN + j];
                if (d < fd[K_NN - 1]) topk_insert(d, mi[(ww * QT + tid) * K_NN + j], fd, fi);
                else break;                        // per-warp lists sorted ascending
            }
        }

        const int lmode = detect_label_mode(label);

        int cnt[NCLS];
#pragma unroll
        for (int c = 0; c < NCLS; ++c) cnt[c] = 0;
#pragma unroll
        for (int j = 0; j < K_NN; ++j) {
            int lab = read_label(label, fi[j], lmode);
#pragma unroll
            for (int c = 0; c < NCLS; ++c) cnt[c] += (lab == c) ? 1 : 0;
        }
        // Ties go to the LARGEST label (reference: reversed argmax) -> use >=.
        int best = -1, win = 0;
#pragma unroll
        for (int c = 0; c < NCLS; ++c) if (cnt[c] >= best) { best = cnt[c]; win = c; }

        out[qb + tid] = (float)win;               // <-- float32 output encoding
    }
}

extern "C" void kernel_launch(void* const* d_in, const int* in_sizes, int n_in,
                              void* d_out, int out_size) {
    // Resolve inputs by SIZE RANK — invariant to ordering and to
    // elements-vs-bytes semantics of in_sizes:
    //   largest = train_pts, 2nd = x, 3rd = train_label, smallest = k (unused).
    int order[8];
    int m = n_in < 8 ? n_in : 8;
    for (int i = 0; i < m; ++i) order[i] = i;
    for (int i = 0; i < m; ++i)
        for (int j = i + 1; j < m; ++j)
            if (in_sizes[order[j]] > in_sizes[order[i]]) {
                int t = order[i]; order[i] = order[j]; order[j] = t;
            }

    const float* tp  = (const float*)d_in[order[0]];
    const float* x   = (const float*)(m > 1 ? d_in[order[1]] : d_in[0]);
    const void*  lab = (m > 2 ? d_in[order[2]] : d_in[0]);

    knn_all<<<N_Q / QT, 256>>>(x, tp, lab, (float*)d_out);
}

// round 9
// speedup vs baseline: 1.1489x; 1.1489x over previous
#include <cuda_runtime.h>

#define N_Q   8192
#define M_T   50000
#define DIM   128
#define K_NN  10
#define NCLS  10
#define QT    32      // queries per block (one per lane)
#define CT    8       // train rows per warp-chunk
#define WARPS 8
#define MS    4       // m-dimension splits -> grid 1024, balanced waves
#define MSPAN (M_T / MS)              // 12500
#define NSLOT (MS * K_NN)             // 40 merge candidates per query

__device__ float g_y2[M_T];
__device__ float g_pd[(size_t)NSLOT * N_Q];
__device__ int   g_pi[(size_t)NSLOT * N_Q];

// Stable sorted-insert: strict < keeps earlier-seen (lower index) on ties,
// matching jax.lax.top_k tie-breaking within a scan stream.
__device__ __forceinline__ void topk_insert(float s, int id,
                                            float (&kd)[K_NN], int (&ki)[K_NN]) {
#pragma unroll
    for (int p = 0; p < K_NN; ++p) {
        if (s < kd[p]) {
            float tf = kd[p]; kd[p] = s; s = tf;
            int   ti = ki[p]; ki[p] = id; id = ti;
        }
    }
}

// Label dtype probe (kept from the passing round): int32/int64/float32-encoded.
__device__ __forceinline__ int detect_label_mode(const void* lp) {
    const long long* i64 = (const long long*)lp;
    bool ok64 = true;
#pragma unroll
    for (int i = 0; i < 32; ++i) { long long v = i64[i]; if (v < 0 || v >= NCLS) ok64 = false; }
    if (ok64) return 1;
    const int* i32 = (const int*)lp;
    bool ok32 = true;
#pragma unroll
    for (int i = 0; i < 32; ++i) { int v = i32[i]; if (v < 0 || v >= NCLS) ok32 = false; }
    if (ok32) return 0;
    const float* f32 = (const float*)lp;
    bool okf = true;
#pragma unroll
    for (int i = 0; i < 32; ++i) {
        float f = f32[i];
        if (!(f >= 0.f && f < (float)NCLS && f == rintf(f))) okf = false;
    }
    if (okf) return 2;
    return 0;
}

__device__ __forceinline__ int read_label(const void* lp, int idx, int mode) {
    if (mode == 1) return (int)((const long long*)lp)[idx];
    if (mode == 2) return (int)rintf(((const float*)lp)[idx]);
    return ((const int*)lp)[idx];
}

// ---------------- Kernel A: y2[m] = sum(train^2) (hoisted out of hot loop) ----
__global__ void y2_kernel(const float* __restrict__ tp) {
    int row  = blockIdx.x * 8 + (threadIdx.x >> 5);
    int lane = threadIdx.x & 31;
    if (row >= M_T) return;
    const float* r = tp + (size_t)row * DIM;
    float s = 0.f;
#pragma unroll
    for (int j = 0; j < 4; ++j) { float v = r[j * 32 + lane]; s = fmaf(v, v, s); }
#pragma unroll
    for (int o = 16; o > 0; o >>= 1) s += __shfl_xor_sync(0xffffffffu, s, o);
    if (lane == 0) g_y2[row] = s;
}

// ---------------- Kernel B: distances + per-block top-k over an m-slice -------
// 48 KB static smem, <=63 regs (4 blocks/SM => 32 warps/SM, single+balanced waves)
__global__ __launch_bounds__(256, 4) void knn_part(
        const float* __restrict__ x, const float* __restrict__ tp) {
    __shared__ float4 sh4[3072];                 // 48 KB, phase-overlaid

    const int tid  = threadIdx.x;
    const int w    = tid >> 5;
    const int lane = tid & 31;
    const int qb   = blockIdx.x * QT;
    const int ms   = blockIdx.y;

    float*  qT  = (float*)sh4;                   // [128][32] transposed (16 KB)
    float4* Tb4 = sh4 + 1024 + w * (CT * 32);    // per-warp 8 rows x 32 float4 (32 KB)

    for (int idx = tid; idx < QT * DIM; idx += 256) {
        int q  = idx >> 7;
        int d0 = idx & (DIM - 1);
        qT[d0 * QT + q] = x[(size_t)(qb + q) * DIM + d0];
    }
    __syncthreads();

    const int mstart = ms * MSPAN;
    const int mend   = mstart + MSPAN;           // M_T % MS == 0

    float kd[K_NN]; int ki[K_NN];
#pragma unroll
    for (int i = 0; i < K_NN; ++i) { kd[i] = 3.4e38f; ki[i] = 0; }

    for (int cb = mstart + w * CT; cb < mend; cb += WARPS * CT) {
#pragma unroll
        for (int it = 0; it < CT; ++it) {
            int g = cb + it;
            float4 v = make_float4(0.f, 0.f, 0.f, 0.f);
            if (g < mend) v = ((const float4*)(tp + (size_t)g * DIM))[lane];
            Tb4[it * 32 + lane] = v;
        }
        __syncwarp();

        float acc[CT];
#pragma unroll
        for (int t = 0; t < CT; ++t) acc[t] = 0.f;

#pragma unroll 1
        for (int sec = 0; sec < 8; ++sec) {           // 16 dims per section
            float qv[16];
#pragma unroll
            for (int j = 0; j < 16; ++j) qv[j] = qT[(sec * 16 + j) * QT + lane];
#pragma unroll
            for (int j4 = 0; j4 < 4; ++j4) {
#pragma unroll
                for (int t = 0; t < CT; ++t) {
                    float4 v = Tb4[t * 32 + sec * 4 + j4];   // warp-uniform broadcast
                    acc[t] = fmaf(qv[j4 * 4 + 0], v.x, acc[t]);
                    acc[t] = fmaf(qv[j4 * 4 + 1], v.y, acc[t]);
                    acc[t] = fmaf(qv[j4 * 4 + 2], v.z, acc[t]);
                    acc[t] = fmaf(qv[j4 * 4 + 3], v.w, acc[t]);
                }
            }
        }

        // score = y2 - 2*dot : same ordering as reference's x2 + y2 - 2*dot.
#pragma unroll
        for (int t = 0; t < CT; ++t) {
            int g = cb + t;
            if (g < mend) {
                float s = fmaf(-2.0f, acc[t], __ldg(&g_y2[g]));
                if (s < kd[K_NN - 1]) topk_insert(s, g, kd, ki);
            }
        }
        __syncwarp();
    }

    // In-block merge of 8 per-warp lists -> one top-10 per query, via smem overlay.
    __syncthreads();
    float* md = (float*)sh4;                      // [WARPS*QT][K_NN] floats
    int*   mi = (int*)(md + WARPS * QT * K_NN);   // [WARPS*QT][K_NN] ints

#pragma unroll
    for (int j = 0; j < K_NN; ++j) {
        md[(w * QT + lane) * K_NN + j] = kd[j];
        mi[(w * QT + lane) * K_NN + j] = ki[j];
    }
    __syncthreads();

    if (tid < QT) {                               // one thread per query
        float fd[K_NN]; int fi[K_NN];
#pragma unroll
        for (int i = 0; i < K_NN; ++i) { fd[i] = 3.4e38f; fi[i] = 0; }
        for (int ww = 0; ww < WARPS; ++ww) {
#pragma unroll
            for (int j = 0; j < K_NN; ++j) {
                float d = md[(ww * QT + tid) * K_NN + j];
                if (d < fd[K_NN - 1]) topk_insert(d, mi[(ww * QT + tid) * K_NN + j], fd, fi);
                else break;                        // per-warp lists sorted ascending
            }
        }
        const int qg = qb + tid;
#pragma unroll
        for (int j = 0; j < K_NN; ++j) {           // coalesced [slot][query]
            g_pd[(size_t)(ms * K_NN + j) * N_Q + qg] = fd[j];
            g_pi[(size_t)(ms * K_NN + j) * N_Q + qg] = fi[j];
        }
    }
}

// ---------------- Kernel C: merge m-splits + vote (float32 output!) ----------
__global__ void merge_vote(const void* __restrict__ label, float* __restrict__ out) {
    int q = blockIdx.x * blockDim.x + threadIdx.x;
    if (q >= N_Q) return;

    float kd[K_NN]; int ki[K_NN];
#pragma unroll
    for (int i = 0; i < K_NN; ++i) { kd[i] = 3.4e38f; ki[i] = 0; }

#pragma unroll 1
    for (int s = 0; s < NSLOT; ++s) {             // coalesced: [slot][query]
        float d = g_pd[(size_t)s * N_Q + q];
        if (d < kd[K_NN - 1]) topk_insert(d, g_pi[(size_t)s * N_Q + q], kd, ki);
    }

    const int lmode = detect_label_mode(label);

    int cnt[NCLS];
#pragma unroll
    for (int c = 0; c < NCLS; ++c) cnt[c] = 0;
#pragma unroll
    for (int j = 0; j < K_NN; ++j) {
        int lab = read_label(label, ki[j], lmode);
#pragma unroll
        for (int c = 0; c < NCLS; ++c) cnt[c] += (lab == c) ? 1 : 0;
    }
    // Ties go to the LARGEST label (reference: reversed argmax) -> use >=.
    int best = -1, win = 0;
#pragma unroll
    for (int c = 0; c < NCLS; ++c) if (cnt[c] >= best) { best = cnt[c]; win = c; }
    out[q] = (float)win;                          // float32 output encoding
}

extern "C" void kernel_launch(void* const* d_in, const int* in_sizes, int n_in,
                              void* d_out, int out_size) {
    // Size-rank resolution: largest=train_pts, 2nd=x, 3rd=labels, smallest=k.
    int order[8];
    int m = n_in < 8 ? n_in : 8;
    for (int i = 0; i < m; ++i) order[i] = i;
    for (int i = 0; i < m; ++i)
        for (int j = i + 1; j < m; ++j)
            if (in_sizes[order[j]] > in_sizes[order[i]]) {
                int t = order[i]; order[i] = order[j]; order[j] = t;
            }

    const float* tp  = (const float*)d_in[order[0]];
    const float* x   = (const float*)(m > 1 ? d_in[order[1]] : d_in[0]);
    const void*  lab = (m > 2 ? d_in[order[2]] : d_in[0]);

    y2_kernel<<<(M_T + 7) / 8, 256>>>(tp);

    dim3 grid(N_Q / QT, MS);
    knn_part<<<grid, 256>>>(x, tp);

    merge_vote<<<(N_Q + 255) / 256, 256>>>(lab, (float*)d_out);
}

// round 12
// speedup vs baseline: 1.5179x; 1.3211x over previous
#include <cuda_runtime.h>
#include <mma.h>
#include <cstdint>

using namespace nvcuda;

#define N_Q    8192
#define M_T    50000
#define DIM    128
#define K_NN   10
#define NCLS   10
#define QTILE  128
#define NTILE  64
#define SPLITS 4
#define SSPAN  (M_T / SPLITS)                     // 12500
#define NTT    ((SSPAN + NTILE - 1) / NTILE)      // 196 (last tile partial: 20 rows)
#define CAND   16
#define NSLOT  (SPLITS * CAND)                    // 64 candidates per query

#define LDA       132                             // padded row stride (528B, 16B-mult)
#define A_FLOATS  (QTILE * LDA)                   // 16896
#define BC_FLOATS 8448                            // max(64*132=8448, 128*64=8192)
#define Y2S_OFF   (A_FLOATS + BC_FLOATS)
#define SMEM_BYTES ((Y2S_OFF + 64) * 4)           // 101,632 B -> 2 blocks/SM

__device__ float g_y2[M_T];
__device__ int   g_ci[(size_t)NSLOT * N_Q];

// ---------------- small helpers ----------------------------------------------
__device__ __forceinline__ void ins16(float s, int id, float (&kd)[CAND], int (&ki)[CAND]) {
#pragma unroll
    for (int p = 0; p < CAND; ++p) {
        if (s < kd[p]) {
            float tf = kd[p]; kd[p] = s; s = tf;
            int   ti = ki[p]; ki[p] = id; id = ti;
        }
    }
}
__device__ __forceinline__ void ins10(float s, int id, float (&kd)[K_NN], int (&ki)[K_NN]) {
#pragma unroll
    for (int p = 0; p < K_NN; ++p) {
        if (s < kd[p]) {
            float tf = kd[p]; kd[p] = s; s = tf;
            int   ti = ki[p]; ki[p] = id; id = ti;
        }
    }
}

// Label dtype probe (int32 / int64 / float32-encoded) — proven in passing rounds.
__device__ __forceinline__ int detect_label_mode(const void* lp) {
    const long long* i64 = (const long long*)lp;
    bool ok64 = true;
#pragma unroll
    for (int i = 0; i < 32; ++i) { long long v = i64[i]; if (v < 0 || v >= NCLS) ok64 = false; }
    if (ok64) return 1;
    const int* i32 = (const int*)lp;
    bool ok32 = true;
#pragma unroll
    for (int i = 0; i < 32; ++i) { int v = i32[i]; if (v < 0 || v >= NCLS) ok32 = false; }
    if (ok32) return 0;
    return 2;
}
__device__ __forceinline__ int read_label(const void* lp, int idx, int mode) {
    if (mode == 1) return (int)((const long long*)lp)[idx];
    if (mode == 2) return (int)rintf(((const float*)lp)[idx]);
    return ((const int*)lp)[idx];
}

// ---------------- Kernel A: y2[m] = sum(train^2) ------------------------------
__global__ void y2_kernel(const float* __restrict__ tp) {
    int row  = blockIdx.x * 8 + (threadIdx.x >> 5);
    int lane = threadIdx.x & 31;
    if (row >= M_T) return;
    const float* r = tp + (size_t)row * DIM;
    float s = 0.f;
#pragma unroll
    for (int j = 0; j < 4; ++j) { float v = r[j * 32 + lane]; s = fmaf(v, v, s); }
#pragma unroll
    for (int o = 16; o > 0; o >>= 1) s += __shfl_xor_sync(0xffffffffu, s, o);
    if (lane == 0) g_y2[row] = s;
}

// ---------------- Kernel B: WMMA tf32 distance filter -> top-16/query/split ---
__global__ __launch_bounds__(256, 2) void knn_tensor(
        const float* __restrict__ x, const float* __restrict__ tp) {
    extern __shared__ float sm[];
    float* As  = sm;                      // [128][132] query tile, resident
    float* Bs  = sm + A_FLOATS;           // [64][132] train tile
    float* Cs  = Bs;                      // overlay: [128][64] scores after MMA
    float* y2s = sm + Y2S_OFF;            // [64]

    const int tid  = threadIdx.x;
    const int w    = tid >> 5;
    const int lane = tid & 31;
    const int qb   = blockIdx.x * QTILE;
    const int sp   = blockIdx.y;
    const int mstart = sp * SSPAN, mend = mstart + SSPAN;
    const int wm = w & 3, wn = w >> 2;    // 4x2 warp grid: 32x32 per warp
    const int row  = tid & 127;           // scan: query row
    const int half = tid >> 7;            // scan: which 32 of 64 scores

    // Load query tile once (row-major, padded).
    for (int i = tid; i < QTILE * 32; i += 256) {
        int r = i >> 5, c = i & 31;
        float4 v = ((const float4*)(x + (size_t)(qb + r) * DIM))[c];
        *(float4*)(As + r * LDA + c * 4) = v;
    }

    float kd[CAND]; int ki[CAND];
#pragma unroll
    for (int i = 0; i < CAND; ++i) { kd[i] = 3.4e38f; ki[i] = 0; }

    for (int t = 0; t < NTT; ++t) {
        const int nb = mstart + t * NTILE;
        __syncthreads();                   // prior Cs fully consumed / A ready

        // Load train tile (row-major, padded); clamp OOB rows (guarded in scan).
        for (int i = tid; i < NTILE * 32; i += 256) {
            int r = i >> 5, c = i & 31;
            int g = nb + r; if (g >= mend) g = mstart;
            float4 v = ((const float4*)(tp + (size_t)g * DIM))[c];
            *(float4*)(Bs + r * LDA + c * 4) = v;
        }
        if (tid < NTILE) {
            int g = nb + tid;
            y2s[tid] = (g < mend) ? g_y2[g] : 0.f;
        }
        __syncthreads();

        // 32x32 per-warp GEMM: C = A(128x128) * B^T(128x64), tf32 fragments.
        wmma::fragment<wmma::accumulator, 16, 16, 8, float> acc[2][2];
#pragma unroll
        for (int mi = 0; mi < 2; ++mi)
#pragma unroll
            for (int ni = 0; ni < 2; ++ni) wmma::fill_fragment(acc[mi][ni], 0.f);

#pragma unroll 1
        for (int k = 0; k < DIM / 8; ++k) {
            wmma::fragment<wmma::matrix_a, 16, 16, 8, wmma::precision::tf32, wmma::row_major> af[2];
            wmma::fragment<wmma::matrix_b, 16, 16, 8, wmma::precision::tf32, wmma::col_major> bf[2];
#pragma unroll
            for (int mi = 0; mi < 2; ++mi) {
                wmma::load_matrix_sync(af[mi], As + (wm * 32 + mi * 16) * LDA + k * 8, LDA);
#pragma unroll
                for (int e = 0; e < af[mi].num_elements; ++e)
                    af[mi].x[e] = wmma::__float_to_tf32(af[mi].x[e]);
            }
#pragma unroll
            for (int ni = 0; ni < 2; ++ni) {
                wmma::load_matrix_sync(bf[ni], Bs + (wn * 32 + ni * 16) * LDA + k * 8, LDA);
#pragma unroll
                for (int e = 0; e < bf[ni].num_elements; ++e)
                    bf[ni].x[e] = wmma::__float_to_tf32(bf[ni].x[e]);
            }
#pragma unroll
            for (int mi = 0; mi < 2; ++mi)
#pragma unroll
                for (int ni = 0; ni < 2; ++ni)
                    wmma::mma_sync(acc[mi][ni], af[mi], bf[ni], acc[mi][ni]);
        }
        __syncthreads();                   // all warps done reading Bs

#pragma unroll
        for (int mi = 0; mi < 2; ++mi)
#pragma unroll
            for (int ni = 0; ni < 2; ++ni)
                wmma::store_matrix_sync(Cs + (wm * 32 + mi * 16) * 64 + wn * 32 + ni * 16,
                                        acc[mi][ni], 64, wmma::mem_row_major);
        __syncthreads();

        // Scan: 2 threads per query row, 32 scores each; rotated index avoids
        // bank conflicts (lanes hit distinct banks every step).
#pragma unroll 1
        for (int jj = 0; jj < 32; ++jj) {
            int j = (jj + lane) & 31;
            int g = nb + half * 32 + j;
            if (g < mend) {
                float s = fmaf(-2.f, Cs[row * 64 + half * 32 + j], y2s[half * 32 + j]);
                if (s < kd[CAND - 1]) ins16(s, g, kd, ki);
            }
        }
    }

    // Merge the two half-lists per row (two-pointer over sorted lists).
    __syncthreads();
    float* md = As;                        // overlay: [128][2][16] floats
    int*   mi = (int*)(As + 4096);         // overlay: [128][2][16] ints
#pragma unroll
    for (int j = 0; j < CAND; ++j) {
        md[(row * 2 + half) * CAND + j] = kd[j];
        mi[(row * 2 + half) * CAND + j] = ki[j];
    }
    __syncthreads();

    if (tid < QTILE) {
        const float* d0 = md + (tid * 2 + 0) * CAND;
        const float* d1 = md + (tid * 2 + 1) * CAND;
        const int*   i0 = mi + (tid * 2 + 0) * CAND;
        const int*   i1 = mi + (tid * 2 + 1) * CAND;
        const int qg = qb + tid;
        int p0 = 0, p1 = 0;
#pragma unroll
        for (int j = 0; j < CAND; ++j) {
            float a = d0[p0], b = d1[p1];
            int   id = (a <= b) ? i0[p0] : i1[p1];
            if (a <= b) ++p0; else ++p1;
            g_ci[(size_t)(sp * CAND + j) * N_Q + qg] = id;
        }
    }
}

// ---------------- Kernel C: exact fp32 rescore of 64 candidates + vote --------
__global__ __launch_bounds__(256) void rescore_vote(
        const float* __restrict__ x, const float* __restrict__ tp,
        const void* __restrict__ label, float* __restrict__ out) {
    __shared__ float4 sq[8][32];
    __shared__ float  sd[8][NSLOT];
    __shared__ int    si[8][NSLOT];

    const int w = threadIdx.x >> 5, lane = threadIdx.x & 31;
    const int q = blockIdx.x * 8 + w;

    sq[w][lane] = ((const float4*)(x + (size_t)q * DIM))[lane];
    __syncwarp();

#pragma unroll
    for (int it = 0; it < NSLOT / 32; ++it) {
        int c = it * 32 + lane;
        int idx = g_ci[(size_t)c * N_Q + q];
        const float4* tr = (const float4*)(tp + (size_t)idx * DIM);
        float dot = 0.f;
#pragma unroll
        for (int j = 0; j < 32; ++j) {
            float4 tv = tr[j];
            float4 qv = sq[w][j];
            dot = fmaf(qv.x, tv.x, dot);
            dot = fmaf(qv.y, tv.y, dot);
            dot = fmaf(qv.z, tv.z, dot);
            dot = fmaf(qv.w, tv.w, dot);
        }
        sd[w][c] = fmaf(-2.f, dot, g_y2[idx]);     // exact fp32 ranking score
        si[w][c] = idx;
    }
    __syncwarp();

    if (lane == 0) {
        float fd[K_NN]; int fi[K_NN];
#pragma unroll
        for (int i = 0; i < K_NN; ++i) { fd[i] = 3.4e38f; fi[i] = 0; }
        for (int c = 0; c < NSLOT; ++c)
            if (sd[w][c] < fd[K_NN - 1]) ins10(sd[w][c], si[w][c], fd, fi);

        const int lmode = detect_label_mode(label);
        int cnt[NCLS];
#pragma unroll
        for (int c = 0; c < NCLS; ++c) cnt[c] = 0;
#pragma unroll
        for (int j = 0; j < K_NN; ++j) {
            int lab = read_label(label, fi[j], lmode);
#pragma unroll
            for (int c = 0; c < NCLS; ++c) cnt[c] += (lab == c) ? 1 : 0;
        }
        int best = -1, win = 0;                    // ties -> largest label
#pragma unroll
        for (int c = 0; c < NCLS; ++c) if (cnt[c] >= best) { best = cnt[c]; win = c; }
        out[q] = (float)win;                       // float32 output encoding
    }
}

extern "C" void kernel_launch(void* const* d_in, const int* in_sizes, int n_in,
                              void* d_out, int out_size) {
    // Size-rank resolution: largest=train_pts, 2nd=x, 3rd=labels, smallest=k.
    int order[8];
    int m = n_in < 8 ? n_in : 8;
    for (int i = 0; i < m; ++i) order[i] = i;
    for (int i = 0; i < m; ++i)
        for (int j = i + 1; j < m; ++j)
            if (in_sizes[order[j]] > in_sizes[order[i]]) {
                int t = order[i]; order[i] = order[j]; order[j] = t;
            }
    const float* tp  = (const float*)d_in[order[0]];
    const float* x   = (const float*)(m > 1 ? d_in[order[1]] : d_in[0]);
    const void*  lab = (m > 2 ? d_in[order[2]] : d_in[0]);

    y2_kernel<<<(M_T + 7) / 8, 256>>>(tp);

    // Idempotent; called every time (no static launch-state guards).
    cudaFuncSetAttribute(knn_tensor, cudaFuncAttributeMaxDynamicSharedMemorySize,
                         SMEM_BYTES);
    dim3 grid(N_Q / QTILE, SPLITS);
    knn_tensor<<<grid, 256, SMEM_BYTES>>>(x, tp);

    rescore_vote<<<N_Q / 8, 256>>>(x, tp, lab, (float*)d_out);
}

// round 13
// speedup vs baseline: 2.4503x; 1.6142x over previous
#include <cuda_runtime.h>
#include <cuda_bf16.h>
#include <mma.h>
#include <cstdint>

using namespace nvcuda;

#define N_Q    8192
#define M_T    50000
#define DIM    128
#define K_NN   10
#define NCLS   10
#define QTILE  128
#define NTILE  64
#define SPLITS 4
#define SSPAN  (M_T / SPLITS)                     // 12500
#define NTT    ((SSPAN + NTILE - 1) / NTILE)      // 196
#define CAND   16
#define NSLOT  (SPLITS * CAND)                    // 64 candidates per query

#define LDH       136                             // bf16 row stride (272B, 16B-mult)
#define A_BYTES   (QTILE * LDH * 2)               // 34816
#define BC_BYTES  32768                           // max(B: 64*136*2=17408, C: 128*64*4)
#define Y2S_BOFF  (A_BYTES + BC_BYTES)            // 67584
#define SMEM_BYTES (Y2S_BOFF + NTILE * 4 + 16)    // ~67856 -> 2 blocks/SM

__device__ float g_y2[M_T];
__device__ int   g_ci[(size_t)NSLOT * N_Q];

// ---------------- small helpers ----------------------------------------------
__device__ __forceinline__ void ins16(float s, int id, float (&kd)[CAND], int (&ki)[CAND]) {
#pragma unroll
    for (int p = 0; p < CAND; ++p) {
        if (s < kd[p]) {
            float tf = kd[p]; kd[p] = s; s = tf;
            int   ti = ki[p]; ki[p] = id; id = ti;
        }
    }
}
__device__ __forceinline__ void ins10(float s, int id, float (&kd)[K_NN], int (&ki)[K_NN]) {
#pragma unroll
    for (int p = 0; p < K_NN; ++p) {
        if (s < kd[p]) {
            float tf = kd[p]; kd[p] = s; s = tf;
            int   ti = ki[p]; ki[p] = id; id = ti;
        }
    }
}

// Label dtype probe (int32 / int64 / float32-encoded) — proven in passing rounds.
__device__ __forceinline__ int detect_label_mode(const void* lp) {
    const long long* i64 = (const long long*)lp;
    bool ok64 = true;
#pragma unroll
    for (int i = 0; i < 32; ++i) { long long v = i64[i]; if (v < 0 || v >= NCLS) ok64 = false; }
    if (ok64) return 1;
    const int* i32 = (const int*)lp;
    bool ok32 = true;
#pragma unroll
    for (int i = 0; i < 32; ++i) { int v = i32[i]; if (v < 0 || v >= NCLS) ok32 = false; }
    if (ok32) return 0;
    return 2;
}
__device__ __forceinline__ int read_label(const void* lp, int idx, int mode) {
    if (mode == 1) return (int)((const long long*)lp)[idx];
    if (mode == 2) return (int)rintf(((const float*)lp)[idx]);
    return ((const int*)lp)[idx];
}

__device__ __forceinline__ void store_bf16x4(__nv_bfloat16* dst, float4 v) {
    __nv_bfloat162 lo = __floats2bfloat162_rn(v.x, v.y);
    __nv_bfloat162 hi = __floats2bfloat162_rn(v.z, v.w);
    *(__nv_bfloat162*)(dst + 0) = lo;
    *(__nv_bfloat162*)(dst + 2) = hi;
}

// ---------------- Kernel A: y2[m] = sum(train^2) ------------------------------
__global__ void y2_kernel(const float* __restrict__ tp) {
    int row  = blockIdx.x * 8 + (threadIdx.x >> 5);
    int lane = threadIdx.x & 31;
    if (row >= M_T) return;
    const float* r = tp + (size_t)row * DIM;
    float s = 0.f;
#pragma unroll
    for (int j = 0; j < 4; ++j) { float v = r[j * 32 + lane]; s = fmaf(v, v, s); }
#pragma unroll
    for (int o = 16; o > 0; o >>= 1) s += __shfl_xor_sync(0xffffffffu, s, o);
    if (lane == 0) g_y2[row] = s;
}

// ---------------- Kernel B: WMMA bf16 distance filter -> top-16/query/split ---
__global__ __launch_bounds__(256, 2) void knn_tensor(
        const float* __restrict__ x, const float* __restrict__ tp) {
    extern __shared__ char smraw[];
    __nv_bfloat16* As = (__nv_bfloat16*)smraw;            // [128][136] bf16, resident
    __nv_bfloat16* Bs = (__nv_bfloat16*)(smraw + A_BYTES);// [64][136] bf16
    float*         Cs = (float*)(smraw + A_BYTES);        // overlay: [128][64] f32
    float*        y2s = (float*)(smraw + Y2S_BOFF);       // [64]

    const int tid  = threadIdx.x;
    const int w    = tid >> 5;
    const int lane = tid & 31;
    const int qb   = blockIdx.x * QTILE;
    const int sp   = blockIdx.y;
    const int mstart = sp * SSPAN, mend = mstart + SSPAN;
    const int wm = w & 3, wn = w >> 2;    // 4x2 warp grid: 32x32 per warp
    const int row  = tid & 127;           // scan: query row
    const int half = tid >> 7;            // scan: which 32 of 64 scores

    // Load query tile once: fp32 global -> bf16 smem (rounded once, here only).
    for (int i = tid; i < QTILE * 32; i += 256) {
        int r = i >> 5, c = i & 31;
        float4 v = ((const float4*)(x + (size_t)(qb + r) * DIM))[c];
        store_bf16x4(As + r * LDH + c * 4, v);
    }

    float kd[CAND]; int ki[CAND];
#pragma unroll
    for (int i = 0; i < CAND; ++i) { kd[i] = 3.4e38f; ki[i] = 0; }

    for (int t = 0; t < NTT; ++t) {
        const int nb = mstart + t * NTILE;
        __syncthreads();                   // prior scan done; B/C region free

        // Load train tile -> bf16; clamp OOB rows (guarded in scan).
        for (int i = tid; i < NTILE * 32; i += 256) {
            int r = i >> 5, c = i & 31;
            int g = nb + r; if (g >= mend) g = mstart;
            float4 v = ((const float4*)(tp + (size_t)g * DIM))[c];
            store_bf16x4(Bs + r * LDH + c * 4, v);
        }
        if (tid < NTILE) {
            int g = nb + tid;
            y2s[tid] = (g < mend) ? g_y2[g] : 0.f;
        }
        __syncthreads();

        // 32x32 per-warp GEMM: C = A(128x128) * B^T(128x64), bf16 (LDSM loads).
        wmma::fragment<wmma::accumulator, 16, 16, 16, float> acc[2][2];
#pragma unroll
        for (int mi = 0; mi < 2; ++mi)
#pragma unroll
            for (int ni = 0; ni < 2; ++ni) wmma::fill_fragment(acc[mi][ni], 0.f);

#pragma unroll
        for (int k = 0; k < DIM / 16; ++k) {
            wmma::fragment<wmma::matrix_a, 16, 16, 16, __nv_bfloat16, wmma::row_major> af[2];
            wmma::fragment<wmma::matrix_b, 16, 16, 16, __nv_bfloat16, wmma::col_major> bf[2];
#pragma unroll
            for (int mi = 0; mi < 2; ++mi)
                wmma::load_matrix_sync(af[mi], As + (wm * 32 + mi * 16) * LDH + k * 16, LDH);
#pragma unroll
            for (int ni = 0; ni < 2; ++ni)
                wmma::load_matrix_sync(bf[ni], Bs + (wn * 32 + ni * 16) * LDH + k * 16, LDH);
#pragma unroll
            for (int mi = 0; mi < 2; ++mi)
#pragma unroll
                for (int ni = 0; ni < 2; ++ni)
                    wmma::mma_sync(acc[mi][ni], af[mi], bf[ni], acc[mi][ni]);
        }
        __syncthreads();                   // all warps done reading Bs (C overlays B)

#pragma unroll
        for (int mi = 0; mi < 2; ++mi)
#pragma unroll
            for (int ni = 0; ni < 2; ++ni)
                wmma::store_matrix_sync(Cs + (wm * 32 + mi * 16) * 64 + wn * 32 + ni * 16,
                                        acc[mi][ni], 64, wmma::mem_row_major);
        __syncthreads();

        // Scan: 2 threads per query row, 32 scores each; rotated index
        // keeps lanes on distinct banks.
#pragma unroll 1
        for (int jj = 0; jj < 32; ++jj) {
            int j = (jj + lane) & 31;
            int g = nb + half * 32 + j;
            if (g < mend) {
                float s = fmaf(-2.f, Cs[row * 64 + half * 32 + j], y2s[half * 32 + j]);
                if (s < kd[CAND - 1]) ins16(s, g, kd, ki);
            }
        }
    }

    // Merge the two half-lists per row (two-pointer over sorted lists).
    __syncthreads();
    float* md = (float*)smraw;             // overlay As: [128][2][16] floats
    int*   mi = (int*)(md + 4096);         // [128][2][16] ints
#pragma unroll
    for (int j = 0; j < CAND; ++j) {
        md[(row * 2 + half) * CAND + j] = kd[j];
        mi[(row * 2 + half) * CAND + j] = ki[j];
    }
    __syncthreads();

    if (tid < QTILE) {
        const float* d0 = md + (tid * 2 + 0) * CAND;
        const float* d1 = md + (tid * 2 + 1) * CAND;
        const int*   i0 = mi + (tid * 2 + 0) * CAND;
        const int*   i1 = mi + (tid * 2 + 1) * CAND;
        const int qg = qb + tid;
        int p0 = 0, p1 = 0;
#pragma unroll
        for (int j = 0; j < CAND; ++j) {
            float a = d0[p0], b = d1[p1];
            int   id = (a <= b) ? i0[p0] : i1[p1];
            if (a <= b) ++p0; else ++p1;
            g_ci[(size_t)(sp * CAND + j) * N_Q + qg] = id;
        }
    }
}

// ---------------- Kernel C: exact fp32 rescore of 64 candidates + vote --------
__global__ __launch_bounds__(256) void rescore_vote(
        const float* __restrict__ x, const float* __restrict__ tp,
        const void* __restrict__ label, float* __restrict__ out) {
    __shared__ float4 sq[8][32];
    __shared__ float  sd[8][NSLOT];
    __shared__ int    si[8][NSLOT];

    const int w = threadIdx.x >> 5, lane = threadIdx.x & 31;
    const int q = blockIdx.x * 8 + w;

    sq[w][lane] = ((const float4*)(x + (size_t)q * DIM))[lane];
    __syncwarp();

#pragma unroll
    for (int it = 0; it < NSLOT / 32; ++it) {
        int c = it * 32 + lane;
        int idx = g_ci[(size_t)c * N_Q + q];
        const float4* tr = (const float4*)(tp + (size_t)idx * DIM);
        float dot = 0.f;
#pragma unroll
        for (int j = 0; j < 32; ++j) {
            float4 tv = tr[j];
            float4 qv = sq[w][j];
            dot = fmaf(qv.x, tv.x, dot);
            dot = fmaf(qv.y, tv.y, dot);
            dot = fmaf(qv.z, tv.z, dot);
            dot = fmaf(qv.w, tv.w, dot);
        }
        sd[w][c] = fmaf(-2.f, dot, g_y2[idx]);     // exact fp32 ranking score
        si[w][c] = idx;
    }
    __syncwarp();

    if (lane == 0) {
        float fd[K_NN]; int fi[K_NN];
#pragma unroll
        for (int i = 0; i < K_NN; ++i) { fd[i] = 3.4e38f; fi[i] = 0; }
        for (int c = 0; c < NSLOT; ++c)
            if (sd[w][c] < fd[K_NN - 1]) ins10(sd[w][c], si[w][c], fd, fi);

        const int lmode = detect_label_mode(label);
        int cnt[NCLS];
#pragma unroll
        for (int c = 0; c < NCLS; ++c) cnt[c] = 0;
#pragma unroll
        for (int j = 0; j < K_NN; ++j) {
            int lab = read_label(label, fi[j], lmode);
#pragma unroll
            for (int c = 0; c < NCLS; ++c) cnt[c] += (lab == c) ? 1 : 0;
        }
        int best = -1, win = 0;                    // ties -> largest label
#pragma unroll
        for (int c = 0; c < NCLS; ++c) if (cnt[c] >= best) { best = cnt[c]; win = c; }
        out[q] = (float)win;                       // float32 output encoding
    }
}

extern "C" void kernel_launch(void* const* d_in, const int* in_sizes, int n_in,
                              void* d_out, int out_size) {
    // Size-rank resolution: largest=train_pts, 2nd=x, 3rd=labels, smallest=k.
    int order[8];
    int m = n_in < 8 ? n_in : 8;
    for (int i = 0; i < m; ++i) order[i] = i;
    for (int i = 0; i < m; ++i)
        for (int j = i + 1; j < m; ++j)
            if (in_sizes[order[j]] > in_sizes[order[i]]) {
                int t = order[i]; order[i] = order[j]; order[j] = t;
            }
    const float* tp  = (const float*)d_in[order[0]];
    const float* x   = (const float*)(m > 1 ? d_in[order[1]] : d_in[0]);
    const void*  lab = (m > 2 ? d_in[order[2]] : d_in[0]);

    y2_kernel<<<(M_T + 7) / 8, 256>>>(tp);

    cudaFuncSetAttribute(knn_tensor, cudaFuncAttributeMaxDynamicSharedMemorySize,
                         SMEM_BYTES);
    dim3 grid(N_Q / QTILE, SPLITS);
    knn_tensor<<<grid, 256, SMEM_BYTES>>>(x, tp);

    rescore_vote<<<N_Q / 8, 256>>>(x, tp, lab, (float*)d_out);
}

// round 14
// speedup vs baseline: 2.5218x; 1.0292x over previous
#include <cuda_runtime.h>
#include <cuda_bf16.h>
#include <mma.h>
#include <cstdint>

using namespace nvcuda;

#define N_Q    8192
#define M_T    50000
#define DIM    128
#define K_NN   10
#define NCLS   10
#define QTILE  128
#define NTILE  64
#define SPLITS 4
#define SSPAN  (M_T / SPLITS)                     // 12500
#define NTT    ((SSPAN + NTILE - 1) / NTILE)      // 196
#define CAND   16
#define NSLOT  (SPLITS * CAND)                    // 64 candidates per query

#define LDH       136                             // bf16 row stride (272B, 16B-mult)
#define A_BYTES   (QTILE * LDH * 2)               // 34816
#define BC_BYTES  32768                           // max(B: 64*136*2, C: 128*64*4)
#define SP_BOFF   (A_BYTES + BC_BYTES)            // y2 partials [64][33] f32
#define Y2S_BOFF  (SP_BOFF + 64 * 33 * 4)
#define SMEM_BYTES (Y2S_BOFF + NTILE * 4 + 16)    // ~76.3 KB -> 2 blocks/SM

__device__ int g_ci[(size_t)NSLOT * N_Q];

// ---------------- small helpers ----------------------------------------------
__device__ __forceinline__ void ins16(float s, int id, float (&kd)[CAND], int (&ki)[CAND]) {
#pragma unroll
    for (int p = 0; p < CAND; ++p) {
        if (s < kd[p]) {
            float tf = kd[p]; kd[p] = s; s = tf;
            int   ti = ki[p]; ki[p] = id; id = ti;
        }
    }
}
__device__ __forceinline__ void ins10(float s, int id, float (&kd)[K_NN], int (&ki)[K_NN]) {
#pragma unroll
    for (int p = 0; p < K_NN; ++p) {
        if (s < kd[p]) {
            float tf = kd[p]; kd[p] = s; s = tf;
            int   ti = ki[p]; ki[p] = id; id = ti;
        }
    }
}

// Label dtype probe (int32 / int64 / float32-encoded) — proven in passing rounds.
__device__ __forceinline__ int detect_label_mode(const void* lp) {
    const long long* i64 = (const long long*)lp;
    bool ok64 = true;
#pragma unroll
    for (int i = 0; i < 32; ++i) { long long v = i64[i]; if (v < 0 || v >= NCLS) ok64 = false; }
    if (ok64) return 1;
    const int* i32 = (const int*)lp;
    bool ok32 = true;
#pragma unroll
    for (int i = 0; i < 32; ++i) { int v = i32[i]; if (v < 0 || v >= NCLS) ok32 = false; }
    if (ok32) return 0;
    return 2;
}
__device__ __forceinline__ int read_label(const void* lp, int idx, int mode) {
    if (mode == 1) return (int)((const long long*)lp)[idx];
    if (mode == 2) return (int)rintf(((const float*)lp)[idx]);
    return ((const int*)lp)[idx];
}

__device__ __forceinline__ void store_bf16x4(__nv_bfloat16* dst, float4 v) {
    __nv_bfloat162 lo = __floats2bfloat162_rn(v.x, v.y);
    __nv_bfloat162 hi = __floats2bfloat162_rn(v.z, v.w);
    *(__nv_bfloat162*)(dst + 0) = lo;
    *(__nv_bfloat162*)(dst + 2) = hi;
}

// ---------------- Kernel 1: WMMA bf16 distance filter (y2 folded in) ---------
__global__ __launch_bounds__(256, 2) void knn_tensor(
        const float* __restrict__ x, const float* __restrict__ tp) {
    extern __shared__ char smraw[];
    __nv_bfloat16* As = (__nv_bfloat16*)smraw;            // [128][136] bf16, resident
    __nv_bfloat16* Bs = (__nv_bfloat16*)(smraw + A_BYTES);// [64][136] bf16
    float*         Cs = (float*)(smraw + A_BYTES);        // overlay: [128][64] f32
    float*         sp = (float*)(smraw + SP_BOFF);        // [64][33] y2 partials
    float*        y2s = (float*)(smraw + Y2S_BOFF);       // [64]

    const int tid  = threadIdx.x;
    const int w    = tid >> 5;
    const int lane = tid & 31;
    const int qb   = blockIdx.x * QTILE;
    const int sp_  = blockIdx.y;
    const int mstart = sp_ * SSPAN, mend = mstart + SSPAN;
    const int wm = w & 3, wn = w >> 2;    // 4x2 warp grid: 32x32 per warp
    const int row  = tid & 127;           // scan: query row
    const int half = tid >> 7;            // scan: which 32 of 64 scores

    // Load query tile once: fp32 global -> bf16 smem.
    for (int i = tid; i < QTILE * 32; i += 256) {
        int r = i >> 5, c = i & 31;
        float4 v = ((const float4*)(x + (size_t)(qb + r) * DIM))[c];
        store_bf16x4(As + r * LDH + c * 4, v);
    }

    float kd[CAND]; int ki[CAND];
#pragma unroll
    for (int i = 0; i < CAND; ++i) { kd[i] = 3.4e38f; ki[i] = 0; }

    for (int t = 0; t < NTT; ++t) {
        const int nb = mstart + t * NTILE;
        __syncthreads();                   // prior scan done; B/C region free

        // Load train tile -> bf16 + per-(row,cgroup) y2 partial (fp32-of-bf16).
#pragma unroll
        for (int it = 0; it < 8; ++it) {
            int i = tid + it * 256;
            int r = i >> 5, c = i & 31;
            int g = nb + r; if (g >= mend) g = mstart;
            float4 v = ((const float4*)(tp + (size_t)g * DIM))[c];
            __nv_bfloat162 lo = __floats2bfloat162_rn(v.x, v.y);
            __nv_bfloat162 hi = __floats2bfloat162_rn(v.z, v.w);
            *(__nv_bfloat162*)(Bs + r * LDH + c * 4 + 0) = lo;
            *(__nv_bfloat162*)(Bs + r * LDH + c * 4 + 2) = hi;
            float ax = __bfloat162float(lo.x), ay = __bfloat162float(lo.y);
            float az = __bfloat162float(hi.x), aw = __bfloat162float(hi.y);
            sp[r * 33 + c] = ax * ax + ay * ay + az * az + aw * aw;
        }
        __syncthreads();

        // Final y2 per row (threads 0-63), runs ahead of warps 0-1's MMA.
        if (tid < NTILE) {
            float s = 0.f;
#pragma unroll
            for (int c = 0; c < 32; ++c) s += sp[tid * 33 + c];
            y2s[tid] = s;
        }

        // 32x32 per-warp GEMM: C = A(128x128) * B^T(128x64), bf16 (LDSM loads).
        wmma::fragment<wmma::accumulator, 16, 16, 16, float> acc[2][2];
#pragma unroll
        for (int mi = 0; mi < 2; ++mi)
#pragma unroll
            for (int ni = 0; ni < 2; ++ni) wmma::fill_fragment(acc[mi][ni], 0.f);

#pragma unroll
        for (int k = 0; k < DIM / 16; ++k) {
            wmma::fragment<wmma::matrix_a, 16, 16, 16, __nv_bfloat16, wmma::row_major> af[2];
            wmma::fragment<wmma::matrix_b, 16, 16, 16, __nv_bfloat16, wmma::col_major> bf[2];
#pragma unroll
            for (int mi = 0; mi < 2; ++mi)
                wmma::load_matrix_sync(af[mi], As + (wm * 32 + mi * 16) * LDH + k * 16, LDH);
#pragma unroll
            for (int ni = 0; ni < 2; ++ni)
                wmma::load_matrix_sync(bf[ni], Bs + (wn * 32 + ni * 16) * LDH + k * 16, LDH);
#pragma unroll
            for (int mi = 0; mi < 2; ++mi)
#pragma unroll
                for (int ni = 0; ni < 2; ++ni)
                    wmma::mma_sync(acc[mi][ni], af[mi], bf[ni], acc[mi][ni]);
        }
        __syncthreads();                   // all warps done reading Bs (C overlays B)

#pragma unroll
        for (int mi = 0; mi < 2; ++mi)
#pragma unroll
            for (int ni = 0; ni < 2; ++ni)
                wmma::store_matrix_sync(Cs + (wm * 32 + mi * 16) * 64 + wn * 32 + ni * 16,
                                        acc[mi][ni], 64, wmma::mem_row_major);
        __syncthreads();

        // Scan: 2 threads per query row, 32 scores each; rotated index keeps
        // lanes on distinct banks; unroll 4 batches LDS for MLP.
#pragma unroll 4
        for (int jj = 0; jj < 32; ++jj) {
            int j = (jj + lane) & 31;
            int g = nb + half * 32 + j;
            if (g < mend) {
                float s = fmaf(-2.f, Cs[row * 64 + half * 32 + j], y2s[half * 32 + j]);
                if (s < kd[CAND - 1]) ins16(s, g, kd, ki);
            }
        }
    }

    // Merge the two half-lists per row (two-pointer over sorted lists).
    __syncthreads();
    float* md = (float*)smraw;             // overlay As: [128][2][16] floats
    int*   mi = (int*)(md + 4096);         // [128][2][16] ints
#pragma unroll
    for (int j = 0; j < CAND; ++j) {
        md[(row * 2 + half) * CAND + j] = kd[j];
        mi[(row * 2 + half) * CAND + j] = ki[j];
    }
    __syncthreads();

    if (tid < QTILE) {
        const float* d0 = md + (tid * 2 + 0) * CAND;
        const float* d1 = md + (tid * 2 + 1) * CAND;
        const int*   i0 = mi + (tid * 2 + 0) * CAND;
        const int*   i1 = mi + (tid * 2 + 1) * CAND;
        const int qg = qb + tid;
        int p0 = 0, p1 = 0;
#pragma unroll
        for (int j = 0; j < CAND; ++j) {
            float a = d0[p0], b = d1[p1];
            int   id = (a <= b) ? i0[p0] : i1[p1];
            if (a <= b) ++p0; else ++p1;
            g_ci[(size_t)(sp_ * CAND + j) * N_Q + qg] = id;
        }
    }
}

// ---------------- Kernel 2: exact fp32 rescore (y2 inline) + vote ------------
__global__ __launch_bounds__(256) void rescore_vote(
        const float* __restrict__ x, const float* __restrict__ tp,
        const void* __restrict__ label, float* __restrict__ out) {
    __shared__ float4 sq[8][32];
    __shared__ float  sd[8][NSLOT];
    __shared__ int    si[8][NSLOT];

    const int w = threadIdx.x >> 5, lane = threadIdx.x & 31;
    const int q = blockIdx.x * 8 + w;

    sq[w][lane] = ((const float4*)(x + (size_t)q * DIM))[lane];
    __syncwarp();

#pragma unroll
    for (int it = 0; it < NSLOT / 32; ++it) {
        int c = it * 32 + lane;
        int idx = g_ci[(size_t)c * N_Q + q];
        const float4* tr = (const float4*)(tp + (size_t)idx * DIM);
        float dot = 0.f, y2e = 0.f;
#pragma unroll
        for (int j = 0; j < 32; ++j) {
            float4 tv = tr[j];
            float4 qv = sq[w][j];
            dot = fmaf(qv.x, tv.x, dot);
            dot = fmaf(qv.y, tv.y, dot);
            dot = fmaf(qv.z, tv.z, dot);
            dot = fmaf(qv.w, tv.w, dot);
            y2e = fmaf(tv.x, tv.x, y2e);
            y2e = fmaf(tv.y, tv.y, y2e);
            y2e = fmaf(tv.z, tv.z, y2e);
            y2e = fmaf(tv.w, tv.w, y2e);
        }
        sd[w][c] = fmaf(-2.f, dot, y2e);           // exact fp32 ranking score
        si[w][c] = idx;
    }
    __syncwarp();

    if (lane == 0) {
        float fd[K_NN]; int fi[K_NN];
#pragma unroll
        for (int i = 0; i < K_NN; ++i) { fd[i] = 3.4e38f; fi[i] = 0; }
        for (int c = 0; c < NSLOT; ++c)
            if (sd[w][c] < fd[K_NN - 1]) ins10(sd[w][c], si[w][c], fd, fi);

        const int lmode = detect_label_mode(label);
        int cnt[NCLS];
#pragma unroll
        for (int c = 0; c < NCLS; ++c) cnt[c] = 0;
#pragma unroll
        for (int j = 0; j < K_NN; ++j) {
            int lab = read_label(label, fi[j], lmode);
#pragma unroll
            for (int c = 0; c < NCLS; ++c) cnt[c] += (lab == c) ? 1 : 0;
        }
        int best = -1, win = 0;                    // ties -> largest label
#pragma unroll
        for (int c = 0; c < NCLS; ++c) if (cnt[c] >= best) { best = cnt[c]; win = c; }
        out[q] = (float)win;                       // float32 output encoding
    }
}

// Alignment pad so ncu's skip-5 lands on knn_tensor (call 2, position 0).
__global__ void dummy_k() {}

extern "C" void kernel_launch(void* const* d_in, const int* in_sizes, int n_in,
                              void* d_out, int out_size) {
    // Size-rank resolution: largest=train_pts, 2nd=x, 3rd=labels, smallest=k.
    int order[8];
    int m = n_in < 8 ? n_in : 8;
    for (int i = 0; i < m; ++i) order[i] = i;
    for (int i = 0; i < m; ++i)
        for (int j = i + 1; j < m; ++j)
            if (in_sizes[order[j]] > in_sizes[order[i]]) {
                int t = order[i]; order[i] = order[j]; order[j] = t;
            }
    const float* tp  = (const float*)d_in[order[0]];
    const float* x   = (const float*)(m > 1 ? d_in[order[1]] : d_in[0]);
    const void*  lab = (m > 2 ? d_in[order[2]] : d_in[0]);

    cudaFuncSetAttribute(knn_tensor, cudaFuncAttributeMaxDynamicSharedMemorySize,
                         SMEM_BYTES);
    dim3 grid(N_Q / QTILE, SPLITS);
    knn_tensor<<<grid, 256, SMEM_BYTES>>>(x, tp);

    rescore_vote<<<N_Q / 8, 256>>>(x, tp, lab, (float*)d_out);

    dummy_k<<<1, 32>>>();
}

// round 16
// speedup vs baseline: 2.8205x; 1.1184x over previous
#include <cuda_runtime.h>
#include <cuda_bf16.h>
#include <mma.h>
#include <cstdint>

using namespace nvcuda;

#define N_Q    8192
#define M_T    50000
#define DIM    128
#define K_NN   10
#define NCLS   10
#define QTILE  128
#define NTILE  128
#define SPLITS 2
#define SSPAN  (M_T / SPLITS)                    // 25000
#define NTT    ((SSPAN + NTILE - 1) / NTILE)     // 196
#define CAND   16
#define NSLOT  (SPLITS * CAND)                   // 32
#define THREADS 512

#define LDH    136                               // bf16 tile row stride (272B)
#define LDC    132                               // f32 C row stride (528B)
#define A_OFF  0
#define B0_OFF 34816
#define B1_OFF 69632
#define C_OFF  104448                            // C: 128*132*4 = 67584
#define Y2_OFF 172032                            // 2 x 128 f32
#define SMEM_TOTAL 173056

__device__ float          g_y2[M_T];
__device__ __nv_bfloat16  g_tpb[(size_t)M_T * DIM];
__device__ __nv_bfloat16  g_xb[(size_t)N_Q * DIM];
__device__ int            g_ci[(size_t)NSLOT * N_Q];

// ---------------- helpers -----------------------------------------------------
__device__ __forceinline__ uint32_t smem_u32(const void* p) {
    uint32_t a;
    asm("{ .reg .u64 t; cvta.to.shared.u64 t, %1; cvt.u32.u64 %0, t; }" : "=r"(a) : "l"(p));
    return a;
}
__device__ __forceinline__ void cp_async16(uint32_t dst, const void* src) {
    asm volatile("cp.async.cg.shared.global [%0], [%1], 16;" :: "r"(dst), "l"(src));
}
__device__ __forceinline__ void cp_async4(uint32_t dst, const void* src) {
    asm volatile("cp.async.ca.shared.global [%0], [%1], 4;" :: "r"(dst), "l"(src));
}
#define CP_COMMIT()  asm volatile("cp.async.commit_group;" ::: "memory")
#define CP_WAIT0()   asm volatile("cp.async.wait_group 0;" ::: "memory")

__device__ __forceinline__ void ins16(float s, int id, float (&kd)[CAND], int (&ki)[CAND]) {
#pragma unroll
    for (int p = 0; p < CAND; ++p) {
        if (s < kd[p]) {
            float tf = kd[p]; kd[p] = s; s = tf;
            int   ti = ki[p]; ki[p] = id; id = ti;
        }
    }
}
__device__ __forceinline__ void ins10(float s, int id, float (&kd)[K_NN], int (&ki)[K_NN]) {
#pragma unroll
    for (int p = 0; p < K_NN; ++p) {
        if (s < kd[p]) {
            float tf = kd[p]; kd[p] = s; s = tf;
            int   ti = ki[p]; ki[p] = id; id = ti;
        }
    }
}

__device__ __forceinline__ int detect_label_mode(const void* lp) {
    const long long* i64 = (const long long*)lp;
    bool ok64 = true;
#pragma unroll
    for (int i = 0; i < 32; ++i) { long long v = i64[i]; if (v < 0 || v >= NCLS) ok64 = false; }
    if (ok64) return 1;
    const int* i32 = (const int*)lp;
    bool ok32 = true;
#pragma unroll
    for (int i = 0; i < 32; ++i) { int v = i32[i]; if (v < 0 || v >= NCLS) ok32 = false; }
    if (ok32) return 0;
    return 2;
}
__device__ __forceinline__ int read_label(const void* lp, int idx, int mode) {
    if (mode == 1) return (int)((const long long*)lp)[idx];
    if (mode == 2) return (int)rintf(((const float*)lp)[idx]);
    return ((const int*)lp)[idx];
}

// ---------------- Kernel 0: one-time cast to bf16 + y2 ------------------------
__global__ void prep_kernel(const float* __restrict__ x, const float* __restrict__ tp) {
    int row  = blockIdx.x * 8 + (threadIdx.x >> 5);
    int lane = threadIdx.x & 31;
    if (row < M_T) {
        float4 v = ((const float4*)(tp + (size_t)row * DIM))[lane];
        __nv_bfloat162 lo = __floats2bfloat162_rn(v.x, v.y);
        __nv_bfloat162 hi = __floats2bfloat162_rn(v.z, v.w);
        *(__nv_bfloat162*)(g_tpb + (size_t)row * DIM + lane * 4 + 0) = lo;
        *(__nv_bfloat162*)(g_tpb + (size_t)row * DIM + lane * 4 + 2) = hi;
        float p = v.x * v.x + v.y * v.y + v.z * v.z + v.w * v.w;
#pragma unroll
        for (int o = 16; o > 0; o >>= 1) p += __shfl_xor_sync(0xffffffffu, p, o);
        if (lane == 0) g_y2[row] = p;
    } else if (row < M_T + N_Q) {
        int xr = row - M_T;
        float4 v = ((const float4*)(x + (size_t)xr * DIM))[lane];
        __nv_bfloat162 lo = __floats2bfloat162_rn(v.x, v.y);
        __nv_bfloat162 hi = __floats2bfloat162_rn(v.z, v.w);
        *(__nv_bfloat162*)(g_xb + (size_t)xr * DIM + lane * 4 + 0) = lo;
        *(__nv_bfloat162*)(g_xb + (size_t)xr * DIM + lane * 4 + 2) = hi;
    }
}

// ---------------- Kernel 1: double-buffered bf16 WMMA filter ------------------
__global__ __launch_bounds__(THREADS, 1) void knn_tensor() {
    extern __shared__ char smraw[];
    const uint32_t sb = smem_u32(smraw);
    __nv_bfloat16* As = (__nv_bfloat16*)(smraw + A_OFF);   // [128][136]
    float*         Cs = (float*)(smraw + C_OFF);           // [128][132]

    const int tid  = threadIdx.x;
    const int w    = tid >> 5;
    const int lane = tid & 31;
    const int wm   = w & 3,  wn   = w >> 2;   // 4x4 warp grid, 32x32 each
    const int srow = tid >> 2, quad = tid & 3; // scan: 4 threads/row, 32 cols each
    const int qb   = blockIdx.x * QTILE;
    const int sp   = blockIdx.y;
    const int mstart = sp * SSPAN, mend = mstart + SSPAN;

    // Prologue: A tile + B buffer 0 + y2 buffer 0, one cp.async group.
#pragma unroll
    for (int it = 0; it < 4; ++it) {
        int ch = tid + it * THREADS;
        int r = ch >> 4, c = ch & 15;
        cp_async16(sb + A_OFF + r * 272 + c * 16, g_xb + (size_t)(qb + r) * DIM + c * 8);
    }
#pragma unroll
    for (int it = 0; it < 4; ++it) {
        int ch = tid + it * THREADS;
        int r = ch >> 4, c = ch & 15;
        int g = mstart + r; if (g >= mend) g = mstart;
        cp_async16(sb + B0_OFF + r * 272 + c * 16, g_tpb + (size_t)g * DIM + c * 8);
    }
    if (tid < NTILE) {
        int g = mstart + tid; if (g >= mend) g = mstart;
        cp_async4(sb + Y2_OFF + tid * 4, g_y2 + g);
    }
    CP_COMMIT();
    CP_WAIT0();
    __syncthreads();

    float kd[CAND]; int ki[CAND];
#pragma unroll
    for (int i = 0; i < CAND; ++i) { kd[i] = 3.4e38f; ki[i] = 0; }

    int p = 0;
    for (int t = 0; t < NTT; ++t, p ^= 1) {
        const int nb = mstart + t * NTILE;

        // Prefetch tile t+1 into the other buffer (hidden behind MMA+scan).
        if (t + 1 < NTT) {
            const int nb1 = nb + NTILE;
            const uint32_t bnext = sb + (p ? B0_OFF : B1_OFF);
#pragma unroll
            for (int it = 0; it < 4; ++it) {
                int ch = tid + it * THREADS;
                int r = ch >> 4, c = ch & 15;
                int g = nb1 + r; if (g >= mend) g = mstart;
                cp_async16(bnext + r * 272 + c * 16, g_tpb + (size_t)g * DIM + c * 8);
            }
            if (tid < NTILE) {
                int g = nb1 + tid; if (g >= mend) g = mstart;
                cp_async4(sb + Y2_OFF + (1 - p) * 512 + tid * 4, g_y2 + g);
            }
        }
        CP_COMMIT();

        // 32x32 per-warp GEMM from the current buffer.
        const __nv_bfloat16* Bsp = (const __nv_bfloat16*)(smraw + (p ? B1_OFF : B0_OFF));
        wmma::fragment<wmma::accumulator, 16, 16, 16, float> acc[2][2];
#pragma unroll
        for (int mi = 0; mi < 2; ++mi)
#pragma unroll
            for (int ni = 0; ni < 2; ++ni) wmma::fill_fragment(acc[mi][ni], 0.f);

#pragma unroll
        for (int k = 0; k < DIM / 16; ++k) {
            wmma::fragment<wmma::matrix_a, 16, 16, 16, __nv_bfloat16, wmma::row_major> af[2];
            wmma::fragment<wmma::matrix_b, 16, 16, 16, __nv_bfloat16, wmma::col_major> bf[2];
#pragma unroll
            for (int mi = 0; mi < 2; ++mi)
                wmma::load_matrix_sync(af[mi], As + (wm * 32 + mi * 16) * LDH + k * 16, LDH);
#pragma unroll
            for (int ni = 0; ni < 2; ++ni)
                wmma::load_matrix_sync(bf[ni], Bsp + (wn * 32 + ni * 16) * LDH + k * 16, LDH);
#pragma unroll
            for (int mi = 0; mi < 2; ++mi)
#pragma unroll
                for (int ni = 0; ni < 2; ++ni)
                    wmma::mma_sync(acc[mi][ni], af[mi], bf[ni], acc[mi][ni]);
        }

#pragma unroll
        for (int mi = 0; mi < 2; ++mi)
#pragma unroll
            for (int ni = 0; ni < 2; ++ni)
                wmma::store_matrix_sync(Cs + (wm * 32 + mi * 16) * LDC + wn * 32 + ni * 16,
                                        acc[mi][ni], LDC, wmma::mem_row_major);
        __syncthreads();                          // C visible to scan

        // Scan: 4 threads/row x 32 cols; rotation -> conflict-free banks.
        const float* y2s = (const float*)(smraw + Y2_OFF + p * 512);
#pragma unroll 4
        for (int jj = 0; jj < 32; ++jj) {
            int j   = (jj + lane) & 31;
            int col = quad * 32 + j;
            int g   = nb + col;
            if (g < mend) {
                float s = fmaf(-2.f, Cs[srow * LDC + col], y2s[col]);
                if (s < kd[CAND - 1]) ins16(s, g, kd, ki);
            }
        }
        CP_WAIT0();                               // next buffer landed
        __syncthreads();                          // scans done; buffers swap safely
    }

    // 4-way merge per row -> top-16 per split, then emit.
    float* md = (float*)(smraw + C_OFF);          // [512][16] floats (32KB)
    int*   mi = (int*)(smraw + C_OFF + 32768);    // [512][16] ints   (32KB)
#pragma unroll
    for (int j = 0; j < CAND; ++j) {
        md[tid * CAND + j] = kd[j];
        mi[tid * CAND + j] = ki[j];
    }
    __syncthreads();

    if (tid < QTILE) {
        int pp[4] = {0, 0, 0, 0};
        const int qg = qb + tid;
#pragma unroll
        for (int j = 0; j < CAND; ++j) {
            float best = md[(tid * 4 + 0) * CAND + pp[0]];
            int   bq   = 0;
#pragma unroll
            for (int q = 1; q < 4; ++q) {
                float d = md[(tid * 4 + q) * CAND + pp[q]];
                if (d < best) { best = d; bq = q; }
            }
            g_ci[(size_t)(sp * CAND + j) * N_Q + qg] = mi[(tid * 4 + bq) * CAND + pp[bq]];
            pp[bq]++;
        }
    }
}

// ---------------- Kernel 2: exact fp32 rescore of 32 candidates + vote --------
__global__ __launch_bounds__(256) void rescore_vote(
        const float* __restrict__ x, const float* __restrict__ tp,
        const void* __restrict__ label, float* __restrict__ out) {
    __shared__ float4 sq[8][32];
    __shared__ float  sd[8][NSLOT];
    __shared__ int    si[8][NSLOT];

    const int w = threadIdx.x >> 5, lane = threadIdx.x & 31;
    const int q = blockIdx.x * 8 + w;

    sq[w][lane] = ((const float4*)(x + (size_t)q * DIM))[lane];
    __syncwarp();

    {
        int c = lane;                              // NSLOT == 32
        int idx = g_ci[(size_t)c * N_Q + q];
        const float4* tr = (const float4*)(tp + (size_t)idx * DIM);
        float dot = 0.f, y2e = 0.f;
#pragma unroll
        for (int j = 0; j < 32; ++j) {
            float4 tv = tr[j];
            float4 qv = sq[w][j];
            dot = fmaf(qv.x, tv.x, dot);
            dot = fmaf(qv.y, tv.y, dot);
            dot = fmaf(qv.z, tv.z, dot);
            dot = fmaf(qv.w, tv.w, dot);
            y2e = fmaf(tv.x, tv.x, y2e);
            y2e = fmaf(tv.y, tv.y, y2e);
            y2e = fmaf(tv.z, tv.z, y2e);
            y2e = fmaf(tv.w, tv.w, y2e);
        }
        sd[w][c] = fmaf(-2.f, dot, y2e);           // exact fp32 ranking score
        si[w][c] = idx;
    }
    __syncwarp();

    if (lane == 0) {
        float fd[K_NN]; int fi[K_NN];
#pragma unroll
        for (int i = 0; i < K_NN; ++i) { fd[i] = 3.4e38f; fi[i] = 0; }
        for (int c = 0; c < NSLOT; ++c)
            if (sd[w][c] < fd[K_NN - 1]) ins10(sd[w][c], si[w][c], fd, fi);

        const int lmode = detect_label_mode(label);
        int cnt[NCLS];
#pragma unroll
        for (int c = 0; c < NCLS; ++c) cnt[c] = 0;
#pragma unroll
        for (int j = 0; j < K_NN; ++j) {
            int lab = read_label(label, fi[j], lmode);
#pragma unroll
            for (int c = 0; c < NCLS; ++c) cnt[c] += (lab == c) ? 1 : 0;
        }
        int best = -1, win = 0;                    // ties -> largest label
#pragma unroll
        for (int c = 0; c < NCLS; ++c) if (cnt[c] >= best) { best = cnt[c]; win = c; }
        out[q] = (float)win;                       // float32 output encoding
    }
}

extern "C" void kernel_launch(void* const* d_in, const int* in_sizes, int n_in,
                              void* d_out, int out_size) {
    // Size-rank resolution: largest=train_pts, 2nd=x, 3rd=labels, smallest=k.
    int order[8];
    int m = n_in < 8 ? n_in : 8;
    for (int i = 0; i < m; ++i) order[i] = i;
    for (int i = 0; i < m; ++i)
        for (int j = i + 1; j < m; ++j)
            if (in_sizes[order[j]] > in_sizes[order[i]]) {
                int t = order[i]; order[i] = order[j]; order[j] = t;
            }
    const float* tp  = (const float*)d_in[order[0]];
    const float* x   = (const float*)(m > 1 ? d_in[order[1]] : d_in[0]);
    const void*  lab = (m > 2 ? d_in[order[2]] : d_in[0]);

    prep_kernel<<<(M_T + N_Q + 7) / 8, 256>>>(x, tp);

    cudaFuncSetAttribute(knn_tensor, cudaFuncAttributeMaxDynamicSharedMemorySize,
                         SMEM_TOTAL);
    dim3 grid(N_Q / QTILE, SPLITS);
    knn_tensor<<<grid, THREADS, SMEM_TOTAL>>>();

    rescore_vote<<<N_Q / 8, 256>>>(x, tp, lab, (float*)d_out);
}

// round 17
// speedup vs baseline: 3.0031x; 1.0647x over previous
#include <cuda_runtime.h>
#include <cuda_bf16.h>
#include <cstdint>

#define N_Q    8192
#define M_T    50000
#define DIM    128
#define K_NN   10
#define NCLS   10
#define QTILE  128
#define NTILE  128
#define SPLITS 2
#define SSPAN  (M_T / SPLITS)                    // 25000
#define NTT    ((SSPAN + NTILE - 1) / NTILE)     // 196
#define CAND   16                                // per scan-thread
#define OUTC   32                                // emitted per split
#define NSLOT  (SPLITS * OUTC)                   // 64
#define THREADS 512

#define LDA8   144                               // fp8 row stride bytes
#define LDC    132                               // f32 C row stride (words)
#define A_OFF  0                                 // 128*144 = 18432
#define B0_OFF 18432
#define B1_OFF 36864
#define C_OFF  55296                             // 128*132*4 = 67584
#define Y2_OFF 122880                            // 2 x 128 f32
#define SMEM_TOTAL 124160

__device__ float   g_y2[M_T];
__device__ uint8_t g_tp8[(size_t)M_T * DIM];
__device__ uint8_t g_x8[(size_t)N_Q * DIM];
__device__ int     g_ci[(size_t)NSLOT * N_Q];

// ---------------- helpers -----------------------------------------------------
__device__ __forceinline__ uint32_t smem_u32(const void* p) {
    uint32_t a;
    asm("{ .reg .u64 t; cvta.to.shared.u64 t, %1; cvt.u32.u64 %0, t; }" : "=r"(a) : "l"(p));
    return a;
}
__device__ __forceinline__ void cp_async16(uint32_t dst, const void* src) {
    asm volatile("cp.async.cg.shared.global [%0], [%1], 16;" :: "r"(dst), "l"(src));
}
__device__ __forceinline__ void cp_async4(uint32_t dst, const void* src) {
    asm volatile("cp.async.ca.shared.global [%0], [%1], 4;" :: "r"(dst), "l"(src));
}
#define CP_COMMIT()  asm volatile("cp.async.commit_group;" ::: "memory")
#define CP_WAIT0()   asm volatile("cp.async.wait_group 0;" ::: "memory")

// fp8 e4m3 MMA: D(16x8,f32) += A(16x32) * B(32x8)  [A row-major, B = Bt[n][k]]
__device__ __forceinline__ void mma_e4m3(float& c0, float& c1, float& c2, float& c3,
                                         uint32_t a0, uint32_t a1, uint32_t a2, uint32_t a3,
                                         uint32_t b0, uint32_t b1) {
    asm volatile(
        "mma.sync.aligned.m16n8k32.row.col.f32.e4m3.e4m3.f32 "
        "{%0,%1,%2,%3}, {%4,%5,%6,%7}, {%8,%9}, {%0,%1,%2,%3};"
        : "+f"(c0), "+f"(c1), "+f"(c2), "+f"(c3)
        : "r"(a0), "r"(a1), "r"(a2), "r"(a3), "r"(b0), "r"(b1));
}

__device__ __forceinline__ uint16_t cvt_e4m3x2(float lo, float hi) {
    uint16_t r;
    asm("cvt.rn.satfinite.e4m3x2.f32 %0, %1, %2;" : "=h"(r) : "f"(hi), "f"(lo));
    return r;
}

__device__ __forceinline__ void ins16(float s, int id, float (&kd)[CAND], int (&ki)[CAND]) {
#pragma unroll
    for (int p = 0; p < CAND; ++p) {
        if (s < kd[p]) {
            float tf = kd[p]; kd[p] = s; s = tf;
            int   ti = ki[p]; ki[p] = id; id = ti;
        }
    }
}
__device__ __forceinline__ void ins10(float s, int id, float (&kd)[K_NN], int (&ki)[K_NN]) {
#pragma unroll
    for (int p = 0; p < K_NN; ++p) {
        if (s < kd[p]) {
            float tf = kd[p]; kd[p] = s; s = tf;
            int   ti = ki[p]; ki[p] = id; id = ti;
        }
    }
}

__device__ __forceinline__ int detect_label_mode(const void* lp) {
    const long long* i64 = (const long long*)lp;
    bool ok64 = true;
#pragma unroll
    for (int i = 0; i < 32; ++i) { long long v = i64[i]; if (v < 0 || v >= NCLS) ok64 = false; }
    if (ok64) return 1;
    const int* i32 = (const int*)lp;
    bool ok32 = true;
#pragma unroll
    for (int i = 0; i < 32; ++i) { int v = i32[i]; if (v < 0 || v >= NCLS) ok32 = false; }
    if (ok32) return 0;
    return 2;
}
__device__ __forceinline__ int read_label(const void* lp, int idx, int mode) {
    if (mode == 1) return (int)((const long long*)lp)[idx];
    if (mode == 2) return (int)rintf(((const float*)lp)[idx]);
    return ((const int*)lp)[idx];
}

// ---------------- Kernel 0: one-time cast to e4m3 + exact fp32 y2 -------------
__global__ void prep_kernel(const float* __restrict__ x, const float* __restrict__ tp) {
    int row  = blockIdx.x * 8 + (threadIdx.x >> 5);
    int lane = threadIdx.x & 31;
    if (row < M_T) {
        float4 v = ((const float4*)(tp + (size_t)row * DIM))[lane];
        uint32_t pk = (uint32_t)cvt_e4m3x2(v.x, v.y) | ((uint32_t)cvt_e4m3x2(v.z, v.w) << 16);
        *(uint32_t*)(g_tp8 + (size_t)row * DIM + lane * 4) = pk;
        float p = v.x * v.x + v.y * v.y + v.z * v.z + v.w * v.w;
#pragma unroll
        for (int o = 16; o > 0; o >>= 1) p += __shfl_xor_sync(0xffffffffu, p, o);
        if (lane == 0) g_y2[row] = p;
    } else if (row < M_T + N_Q) {
        int xr = row - M_T;
        float4 v = ((const float4*)(x + (size_t)xr * DIM))[lane];
        uint32_t pk = (uint32_t)cvt_e4m3x2(v.x, v.y) | ((uint32_t)cvt_e4m3x2(v.z, v.w) << 16);
        *(uint32_t*)(g_x8 + (size_t)xr * DIM + lane * 4) = pk;
    }
}

// ---------------- Kernel 1: fp8 MMA distance filter ---------------------------
__global__ __launch_bounds__(THREADS, 1) void knn_tensor() {
    extern __shared__ char smraw[];
    const uint32_t sb = smem_u32(smraw);
    float* Cs = (float*)(smraw + C_OFF);          // [128][132]

    const int tid  = threadIdx.x;
    const int w    = tid >> 5;
    const int lane = tid & 31;
    const int g8   = lane >> 2;                   // mma group id (0..7)
    const int tig4 = (lane & 3) * 4;              // byte offset within k-quad
    const int wm   = w & 3,  wn = w >> 2;         // 4x4 warp grid, 32x32 C each
    const int srow = tid >> 2, quad = tid & 3;    // scan: 4 threads/row
    const int qb   = blockIdx.x * QTILE;
    const int sp   = blockIdx.y;
    const int mstart = sp * SSPAN, mend = mstart + SSPAN;

    // Prologue: A tile + B buffer 0 + y2 buffer 0 (one cp.async group).
#pragma unroll
    for (int it = 0; it < 2; ++it) {
        int ch = tid + it * THREADS;              // 1024 chunks of 16B
        int r = ch >> 3, c = ch & 7;
        cp_async16(sb + A_OFF + r * LDA8 + c * 16, g_x8 + (size_t)(qb + r) * DIM + c * 16);
    }
#pragma unroll
    for (int it = 0; it < 2; ++it) {
        int ch = tid + it * THREADS;
        int r = ch >> 3, c = ch & 7;
        int g = mstart + r; if (g >= mend) g = mstart;
        cp_async16(sb + B0_OFF + r * LDA8 + c * 16, g_tp8 + (size_t)g * DIM + c * 16);
    }
    if (tid < NTILE) {
        int g = mstart + tid; if (g >= mend) g = mstart;
        cp_async4(sb + Y2_OFF + tid * 4, g_y2 + g);
    }
    CP_COMMIT();
    CP_WAIT0();
    __syncthreads();

    float kd[CAND]; int ki[CAND];
#pragma unroll
    for (int i = 0; i < CAND; ++i) { kd[i] = 3.4e38f; ki[i] = 0; }

    int p = 0;
    for (int t = 0; t < NTT; ++t, p ^= 1) {
        const int nb = mstart + t * NTILE;

        if (t + 1 < NTT) {                        // prefetch next B + y2
            const int nb1 = nb + NTILE;
            const uint32_t bnext = sb + (p ? B0_OFF : B1_OFF);
#pragma unroll
            for (int it = 0; it < 2; ++it) {
                int ch = tid + it * THREADS;
                int r = ch >> 3, c = ch & 7;
                int g = nb1 + r; if (g >= mend) g = mstart;
                cp_async16(bnext + r * LDA8 + c * 16, g_tp8 + (size_t)g * DIM + c * 16);
            }
            if (tid < NTILE) {
                int g = nb1 + tid; if (g >= mend) g = mstart;
                cp_async4(sb + Y2_OFF + (1 - p) * 512 + tid * 4, g_y2 + g);
            }
        }
        CP_COMMIT();

        // fp8 GEMM: per warp 32x32 of C; 2 m-frags x 4 n-frags, k = 4 x 32.
        const char* Asm = smraw + A_OFF;
        const char* Bsm = smraw + (p ? B1_OFF : B0_OFF);
        float c0[2][4], c1[2][4], c2[2][4], c3[2][4];
#pragma unroll
        for (int mi = 0; mi < 2; ++mi)
#pragma unroll
            for (int ni = 0; ni < 4; ++ni)
                c0[mi][ni] = c1[mi][ni] = c2[mi][ni] = c3[mi][ni] = 0.f;

#pragma unroll
        for (int ks = 0; ks < 4; ++ks) {
            const int koff = ks * 32;
            uint32_t a[2][4], b[4][2];
#pragma unroll
            for (int mi = 0; mi < 2; ++mi) {
                const char* ar = Asm + (wm * 32 + mi * 16 + g8) * LDA8 + tig4 + koff;
                a[mi][0] = *(const uint32_t*)(ar);
                a[mi][1] = *(const uint32_t*)(ar + 8 * LDA8);
                a[mi][2] = *(const uint32_t*)(ar + 16);
                a[mi][3] = *(const uint32_t*)(ar + 8 * LDA8 + 16);
            }
#pragma unroll
            for (int ni = 0; ni < 4; ++ni) {
                const char* br = Bsm + (wn * 32 + ni * 8 + g8) * LDA8 + tig4 + koff;
                b[ni][0] = *(const uint32_t*)(br);
                b[ni][1] = *(const uint32_t*)(br + 16);
            }
#pragma unroll
            for (int mi = 0; mi < 2; ++mi)
#pragma unroll
                for (int ni = 0; ni < 4; ++ni)
                    mma_e4m3(c0[mi][ni], c1[mi][ni], c2[mi][ni], c3[mi][ni],
                             a[mi][0], a[mi][1], a[mi][2], a[mi][3],
                             b[ni][0], b[ni][1]);
        }

        // Store C to smem: c0,c1 -> row g8; c2,c3 -> row g8+8; cols 2*tig.
#pragma unroll
        for (int mi = 0; mi < 2; ++mi)
#pragma unroll
            for (int ni = 0; ni < 4; ++ni) {
                int r0 = wm * 32 + mi * 16 + g8;
                int cc = wn * 32 + ni * 8 + (lane & 3) * 2;
                Cs[r0 * LDC + cc]           = c0[mi][ni];
                Cs[r0 * LDC + cc + 1]       = c1[mi][ni];
                Cs[(r0 + 8) * LDC + cc]     = c2[mi][ni];
                Cs[(r0 + 8) * LDC + cc + 1] = c3[mi][ni];
            }
        __syncthreads();

        // Scan: 4 threads/row x 32 cols; rotation keeps banks distinct.
        const float* y2s = (const float*)(smraw + Y2_OFF + p * 512);
#pragma unroll 4
        for (int jj = 0; jj < 32; ++jj) {
            int j   = (jj + lane) & 31;
            int col = quad * 32 + j;
            int g   = nb + col;
            if (g < mend) {
                float s = fmaf(-2.f, Cs[srow * LDC + col], y2s[col]);
                if (s < kd[CAND - 1]) ins16(s, g, kd, ki);
            }
        }
        CP_WAIT0();
        __syncthreads();
    }

    // 4-way guarded merge per row -> top-32 per split.
    float* md = (float*)(smraw + C_OFF);          // [512][16] floats
    int*   mi = (int*)(smraw + C_OFF + 32768);    // [512][16] ints
#pragma unroll
    for (int j = 0; j < CAND; ++j) {
        md[tid * CAND + j] = kd[j];
        mi[tid * CAND + j] = ki[j];
    }
    __syncthreads();

    if (tid < QTILE) {
        int pp[4] = {0, 0, 0, 0};
        const int qg = qb + tid;
#pragma unroll 1
        for (int j = 0; j < OUTC; ++j) {
            float best = 3.4e38f;
            int   bq   = 0;
#pragma unroll
            for (int q = 0; q < 4; ++q) {
                float d = (pp[q] < CAND) ? md[(tid * 4 + q) * CAND + pp[q]] : 3.4e38f;
                if (d < best) { best = d; bq = q; }
            }
            g_ci[(size_t)(sp * OUTC + j) * N_Q + qg] = mi[(tid * 4 + bq) * CAND + pp[bq]];
            pp[bq]++;
        }
    }
}

// ---------------- Kernel 2: exact fp32 rescore of 64 candidates + vote --------
__global__ __launch_bounds__(256) void rescore_vote(
        const float* __restrict__ x, const float* __restrict__ tp,
        const void* __restrict__ label, float* __restrict__ out) {
    __shared__ float4 sq[8][32];
    __shared__ float  sd[8][NSLOT];
    __shared__ int    si[8][NSLOT];

    const int w = threadIdx.x >> 5, lane = threadIdx.x & 31;
    const int q = blockIdx.x * 8 + w;

    sq[w][lane] = ((const float4*)(x + (size_t)q * DIM))[lane];
    __syncwarp();

#pragma unroll
    for (int it = 0; it < NSLOT / 32; ++it) {
        int c = it * 32 + lane;
        int idx = g_ci[(size_t)c * N_Q + q];
        const float4* tr = (const float4*)(tp + (size_t)idx * DIM);
        float dot = 0.f, y2e = 0.f;
#pragma unroll
        for (int j = 0; j < 32; ++j) {
            float4 tv = tr[j];
            float4 qv = sq[w][j];
            dot = fmaf(qv.x, tv.x, dot);
            dot = fmaf(qv.y, tv.y, dot);
            dot = fmaf(qv.z, tv.z, dot);
            dot = fmaf(qv.w, tv.w, dot);
            y2e = fmaf(tv.x, tv.x, y2e);
            y2e = fmaf(tv.y, tv.y, y2e);
            y2e = fmaf(tv.z, tv.z, y2e);
            y2e = fmaf(tv.w, tv.w, y2e);
        }
        sd[w][c] = fmaf(-2.f, dot, y2e);           // exact fp32 ranking score
        si[w][c] = idx;
    }
    __syncwarp();

    if (lane == 0) {
        float fd[K_NN]; int fi[K_NN];
#pragma unroll
        for (int i = 0; i < K_NN; ++i) { fd[i] = 3.4e38f; fi[i] = 0; }
        for (int c = 0; c < NSLOT; ++c)
            if (sd[w][c] < fd[K_NN - 1]) ins10(sd[w][c], si[w][c], fd, fi);

        const int lmode = detect_label_mode(label);
        int cnt[NCLS];
#pragma unroll
        for (int c = 0; c < NCLS; ++c) cnt[c] = 0;
#pragma unroll
        for (int j = 0; j < K_NN; ++j) {
            int lab = read_label(label, fi[j], lmode);
#pragma unroll
            for (int c = 0; c < NCLS; ++c) cnt[c] += (lab == c) ? 1 : 0;
        }
        int best = -1, win = 0;                    // ties -> largest label
#pragma unroll
        for (int c = 0; c < NCLS; ++c) if (cnt[c] >= best) { best = cnt[c]; win = c; }
        out[q] = (float)win;                       // float32 output encoding
    }
}

extern "C" void kernel_launch(void* const* d_in, const int* in_sizes, int n_in,
                              void* d_out, int out_size) {
    // Size-rank resolution: largest=train_pts, 2nd=x, 3rd=labels, smallest=k.
    int order[8];
    int m = n_in < 8 ? n_in : 8;
    for (int i = 0; i < m; ++i) order[i] = i;
    for (int i = 0; i < m; ++i)
        for (int j = i + 1; j < m; ++j)
            if (in_sizes[order[j]] > in_sizes[order[i]]) {
                int t = order[i]; order[i] = order[j]; order[j] = t;
            }
    const float* tp  = (const float*)d_in[order[0]];
    const float* x   = (const float*)(m > 1 ? d_in[order[1]] : d_in[0]);
    const void*  lab = (m > 2 ? d_in[order[2]] : d_in[0]);

    prep_kernel<<<(M_T + N_Q + 7) / 8, 256>>>(x, tp);

    cudaFuncSetAttribute(knn_tensor, cudaFuncAttributeMaxDynamicSharedMemorySize,
                         SMEM_TOTAL);
    dim3 grid(N_Q / QTILE, SPLITS);
    knn_tensor<<<grid, THREADS, SMEM_TOTAL>>>();

    rescore_vote<<<N_Q / 8, 256>>>(x, tp, lab, (float*)d_out);
}